// round 14
// baseline (speedup 1.0000x reference)
#include <cuda_runtime.h>
#include <cuda_bf16.h>
#include <cstdint>

#define B_  4
#define SQ  2048
#define SK_ 2048
#define DD  512
#define H_  8
#define HD  64
#define SCALE 0.125f
#define EPSLN 1e-5f

#define NTOK (B_*SQ)            // 8192
#define LINSZ (NTOK*DD)         // 4194304

// Scratch (device globals: allocation-free rule)
__device__ float g_qlin[LINSZ];
__device__ float g_ctx[LINSZ];
__device__ float g_oproj[LINSZ];
__device__ __nv_bfloat16 g_qh[LINSZ], g_ql[LINSZ];
__device__ __nv_bfloat16 g_kh[LINSZ], g_kl[LINSZ];
__device__ __nv_bfloat16 g_vh[LINSZ], g_vl[LINSZ];

// ---------------------------------------------------------------------------
// Helpers
// ---------------------------------------------------------------------------
__device__ __forceinline__ void split2(float x, float y, uint32_t& hi, uint32_t& lo) {
    __nv_bfloat16 hx = __float2bfloat16(x), hy = __float2bfloat16(y);
    float rx = x - __bfloat162float(hx);
    float ry = y - __bfloat162float(hy);
    __nv_bfloat16 lx = __float2bfloat16(rx), ly = __float2bfloat16(ry);
    hi = ((uint32_t)__bfloat16_as_ushort(hy) << 16) | __bfloat16_as_ushort(hx);
    lo = ((uint32_t)__bfloat16_as_ushort(ly) << 16) | __bfloat16_as_ushort(lx);
}

__device__ __forceinline__ void mma16816(float* c, const uint32_t* a, const uint32_t* b) {
    asm volatile(
        "mma.sync.aligned.m16n8k16.row.col.f32.bf16.bf16.f32 "
        "{%0,%1,%2,%3},{%4,%5,%6,%7},{%8,%9},{%0,%1,%2,%3};\n"
        : "+f"(c[0]), "+f"(c[1]), "+f"(c[2]), "+f"(c[3])
        : "r"(a[0]), "r"(a[1]), "r"(a[2]), "r"(a[3]), "r"(b[0]), "r"(b[1]));
}

__device__ __forceinline__ uint32_t sh_addr(const void* p) {
    return (uint32_t)__cvta_generic_to_shared(p);
}

__device__ __forceinline__ void ldsm4(uint32_t* r, uint32_t addr) {
    asm volatile("ldmatrix.sync.aligned.m8n8.x4.shared.b16 {%0,%1,%2,%3},[%4];\n"
                 : "=r"(r[0]), "=r"(r[1]), "=r"(r[2]), "=r"(r[3]) : "r"(addr) : "memory");
}

__device__ __forceinline__ void ldsm4t(uint32_t* r, uint32_t addr) {
    asm volatile("ldmatrix.sync.aligned.m8n8.x4.trans.shared.b16 {%0,%1,%2,%3},[%4];\n"
                 : "=r"(r[0]), "=r"(r[1]), "=r"(r[2]), "=r"(r[3]) : "r"(addr) : "memory");
}

// ---------------------------------------------------------------------------
// Linear: Y = X @ W^T + bias. fp32 out optional; split-bf16 hi/lo out optional.
// (unchanged from R10 passing kernel)
// ---------------------------------------------------------------------------
__global__ __launch_bounds__(256) void linear_mma(
    const float* __restrict__ X, const float* __restrict__ W,
    const float* __restrict__ bias, float* __restrict__ Y,
    __nv_bfloat16* __restrict__ Yh, __nv_bfloat16* __restrict__ Yl,
    int K, int N)
{
    __shared__ __nv_bfloat16 sAh[128 * 36], sAl[128 * 36];
    __shared__ __nv_bfloat16 sBh[128 * 36], sBl[128 * 36];
    const int m0 = blockIdx.y * 128;
    const int n0 = blockIdx.x * 128;
    const float* A  = X + (size_t)m0 * K;
    const float* Bm = W + (size_t)n0 * K;

    const int tid  = threadIdx.x;
    const int wid  = tid >> 5, lane = tid & 31;
    const int wm   = wid >> 2;
    const int wn   = wid & 3;
    const int grp  = lane >> 2;
    const int tig  = lane & 3;

    float acc[4][4][4] = {};

    for (int k0 = 0; k0 < K; k0 += 32) {
        #pragma unroll
        for (int i = 0; i < 4; i++) {
            int s   = tid + i * 256;
            int row = s >> 3;
            int c   = s & 7;
            float4 av = *(const float4*)(A + (size_t)row * K + k0 + c * 4);
            uint32_t h0, l0, h1, l1;
            split2(av.x, av.y, h0, l0);
            split2(av.z, av.w, h1, l1);
            uint32_t* ph = (uint32_t*)(sAh + row * 36 + c * 4);
            uint32_t* pl = (uint32_t*)(sAl + row * 36 + c * 4);
            ph[0] = h0; ph[1] = h1;
            pl[0] = l0; pl[1] = l1;

            float4 bv = *(const float4*)(Bm + (size_t)row * K + k0 + c * 4);
            split2(bv.x, bv.y, h0, l0);
            split2(bv.z, bv.w, h1, l1);
            ph = (uint32_t*)(sBh + row * 36 + c * 4);
            pl = (uint32_t*)(sBl + row * 36 + c * 4);
            ph[0] = h0; ph[1] = h1;
            pl[0] = l0; pl[1] = l1;
        }
        __syncthreads();

        #pragma unroll
        for (int ks = 0; ks < 2; ks++) {
            const int kb = ks * 16 + tig * 2;
            uint32_t ah[4][4], al[4][4];
            #pragma unroll
            for (int i = 0; i < 4; i++) {
                int r0 = wm * 64 + i * 16 + grp;
                ah[i][0] = *(const uint32_t*)(sAh + r0 * 36 + kb);
                ah[i][1] = *(const uint32_t*)(sAh + (r0 + 8) * 36 + kb);
                ah[i][2] = *(const uint32_t*)(sAh + r0 * 36 + kb + 8);
                ah[i][3] = *(const uint32_t*)(sAh + (r0 + 8) * 36 + kb + 8);
                al[i][0] = *(const uint32_t*)(sAl + r0 * 36 + kb);
                al[i][1] = *(const uint32_t*)(sAl + (r0 + 8) * 36 + kb);
                al[i][2] = *(const uint32_t*)(sAl + r0 * 36 + kb + 8);
                al[i][3] = *(const uint32_t*)(sAl + (r0 + 8) * 36 + kb + 8);
            }
            uint32_t bh[4][2], bl[4][2];
            #pragma unroll
            for (int j = 0; j < 4; j++) {
                int nr = wn * 32 + j * 8 + grp;
                bh[j][0] = *(const uint32_t*)(sBh + nr * 36 + kb);
                bh[j][1] = *(const uint32_t*)(sBh + nr * 36 + kb + 8);
                bl[j][0] = *(const uint32_t*)(sBl + nr * 36 + kb);
                bl[j][1] = *(const uint32_t*)(sBl + nr * 36 + kb + 8);
            }
            #pragma unroll
            for (int i = 0; i < 4; i++)
                #pragma unroll
                for (int j = 0; j < 4; j++) {
                    mma16816(acc[i][j], ah[i], bh[j]);
                    mma16816(acc[i][j], ah[i], bl[j]);
                    mma16816(acc[i][j], al[i], bh[j]);
                }
        }
        __syncthreads();
    }

    #pragma unroll
    for (int i = 0; i < 4; i++) {
        #pragma unroll
        for (int j = 0; j < 4; j++) {
            int r  = m0 + wm * 64 + i * 16 + grp;
            int cN = n0 + wn * 32 + j * 8 + tig * 2;
            float bv0 = bias[cN], bv1 = bias[cN + 1];
            float v00 = acc[i][j][0] + bv0, v01 = acc[i][j][1] + bv1;
            float v10 = acc[i][j][2] + bv0, v11 = acc[i][j][3] + bv1;
            size_t o0 = (size_t)r * N + cN;
            size_t o1 = (size_t)(r + 8) * N + cN;
            if (Y) {
                Y[o0] = v00; Y[o0 + 1] = v01;
                Y[o1] = v10; Y[o1 + 1] = v11;
            }
            if (Yh) {
                uint32_t h0, l0, h1, l1;
                split2(v00, v01, h0, l0);
                split2(v10, v11, h1, l1);
                *(uint32_t*)(Yh + o0) = h0; *(uint32_t*)(Yl + o0) = l0;
                *(uint32_t*)(Yh + o1) = h1; *(uint32_t*)(Yl + o1) = l1;
            }
        }
    }
}

// ---------------------------------------------------------------------------
// scores: unchanged from R10 passing kernel.
// ---------------------------------------------------------------------------
__global__ __launch_bounds__(256, 2) void scores_mma(
    const __nv_bfloat16* __restrict__ qh, const __nv_bfloat16* __restrict__ ql,
    const __nv_bfloat16* __restrict__ kh, const __nv_bfloat16* __restrict__ kl,
    float* __restrict__ attn)
{
    __shared__ __nv_bfloat16 sQh[128 * 40], sQl[128 * 40];
    __shared__ __nv_bfloat16 sKh[128 * 40], sKl[128 * 40];
    const int tid = threadIdx.x;
    const int wid = tid >> 5, lane = tid & 31;
    const int bh = blockIdx.z, b = bh >> 3, h = bh & 7;
    const int m0 = blockIdx.y * 128, n0 = blockIdx.x * 128;

    const size_t qbase = (size_t)(b * SQ + m0) * DD + h * HD;
    const size_t kbase = (size_t)(b * SK_ + n0) * DD + h * HD;

    const int wm = wid >> 2, wn = wid & 3;
    const int grp = lane >> 2, tig = lane & 3;
    const int lrow = lane & 15, lcol = (lane >> 4) * 8;

    float acc[4][4][4] = {};

    #pragma unroll
    for (int kh0 = 0; kh0 < HD; kh0 += 32) {
        if (kh0) __syncthreads();
        #pragma unroll
        for (int i = 0; i < 2; i++) {
            int c = tid + i * 256;
            int row = c >> 2, off = (c & 3) * 8;
            size_t g = (size_t)row * DD + kh0 + off;
            *(uint4*)&sQh[row * 40 + off] = *(const uint4*)&qh[qbase + g];
            *(uint4*)&sQl[row * 40 + off] = *(const uint4*)&ql[qbase + g];
            *(uint4*)&sKh[row * 40 + off] = *(const uint4*)&kh[kbase + g];
            *(uint4*)&sKl[row * 40 + off] = *(const uint4*)&kl[kbase + g];
        }
        __syncthreads();

        #pragma unroll
        for (int ks = 0; ks < 2; ks++) {
            const int kc = ks * 16 + lcol;
            uint32_t ah[4][4], al[4][4];
            #pragma unroll
            for (int i = 0; i < 4; i++) {
                int r = wm * 64 + i * 16 + lrow;
                ldsm4(ah[i], sh_addr(&sQh[r * 40 + kc]));
                ldsm4(al[i], sh_addr(&sQl[r * 40 + kc]));
            }
            uint32_t bhf[2][4], blf[2][4];
            #pragma unroll
            for (int c = 0; c < 2; c++) {
                int r = wn * 32 + c * 16 + lrow;
                ldsm4(bhf[c], sh_addr(&sKh[r * 40 + kc]));
                ldsm4(blf[c], sh_addr(&sKl[r * 40 + kc]));
            }
            #pragma unroll
            for (int i = 0; i < 4; i++)
                #pragma unroll
                for (int c = 0; c < 2; c++)
                    #pragma unroll
                    for (int hf = 0; hf < 2; hf++) {
                        uint32_t bH[2] = {bhf[c][hf], bhf[c][hf + 2]};
                        uint32_t bL[2] = {blf[c][hf], blf[c][hf + 2]};
                        float* a = acc[i][c * 2 + hf];
                        mma16816(a, ah[i], bH);
                        mma16816(a, ah[i], bL);
                        mma16816(a, al[i], bH);
                    }
        }
    }

    float* obase = attn + (size_t)bh * SQ * SK_ + (size_t)m0 * SK_ + n0;
    #pragma unroll
    for (int i = 0; i < 4; i++)
        #pragma unroll
        for (int j = 0; j < 4; j++) {
            int r  = wm * 64 + i * 16 + grp;
            int cN = wn * 32 + j * 8 + tig * 2;
            float* o0 = obase + (size_t)r * SK_ + cN;
            float* o1 = obase + (size_t)(r + 8) * SK_ + cN;
            o0[0] = acc[i][j][0] * SCALE; o0[1] = acc[i][j][1] * SCALE;
            o1[0] = acc[i][j][2] * SCALE; o1[1] = acc[i][j][3] * SCALE;
        }
}

// ---------------------------------------------------------------------------
// FUSED softmax + attn-write + PV.  Per (bh, 128-row m-tile):
// pass 1: stream raw scores, online row max+sum (coalesced, __expf).
// pass 2: re-read S tiles (L2-hot), p = exp(s-mx)*inv -> write attn once,
//         split-bf16 into smem, MMA with V (trans-ldsm). O = P@V directly.
// In-place safe: each block owns disjoint rows; writes happen after both
// reads of an element within the same staging iteration.
// ---------------------------------------------------------------------------
__global__ __launch_bounds__(256, 2) void smpv_mma(
    float* __restrict__ attn,
    const __nv_bfloat16* __restrict__ vh, const __nv_bfloat16* __restrict__ vl,
    float* __restrict__ ctx)
{
    __shared__ __nv_bfloat16 sPh[128 * 40], sPl[128 * 40];
    __shared__ __nv_bfloat16 sVh[32 * 72],  sVl[32 * 72];
    __shared__ float s_mx[128], s_inv[128];

    const int tid = threadIdx.x;
    const int wid = tid >> 5, lane = tid & 31;
    const int bh = blockIdx.y, b = bh >> 3, h = bh & 7;
    const int m0 = blockIdx.x * 128;

    float* S = attn + (size_t)bh * SQ * SK_ + (size_t)m0 * SK_;
    const size_t vbase = (size_t)b * SK_ * DD + h * HD;

    // ---- pass 1: online max+sum per row ----
    {
        const int rgrp = lane >> 3;          // 0..3 row within warp's group
        const int lx   = lane & 7;           // 0..7 lane within row
        #pragma unroll
        for (int it = 0; it < 4; it++) {
            int row = it * 32 + wid * 4 + rgrp;
            const float4* Sr = (const float4*)(S + (size_t)row * SK_);
            float m = -1e30f, sum = 0.0f;
            #pragma unroll 4
            for (int kk = 0; kk < 64; kk++) {
                float4 v = Sr[kk * 8 + lx];
                float mt = fmaxf(fmaxf(v.x, v.y), fmaxf(v.z, v.w));
                if (mt > m) {
                    sum *= __expf(m - mt);
                    m = mt;
                }
                sum += __expf(v.x - m) + __expf(v.y - m)
                     + __expf(v.z - m) + __expf(v.w - m);
            }
            #pragma unroll
            for (int o = 1; o < 8; o <<= 1) {
                float mo = __shfl_xor_sync(~0u, m, o);
                float so = __shfl_xor_sync(~0u, sum, o);
                float mn = fmaxf(m, mo);
                sum = sum * __expf(m - mn) + so * __expf(mo - mn);
                m = mn;
            }
            if (lx == 0) {
                s_mx[row]  = m;
                s_inv[row] = 1.0f / sum;
            }
        }
    }
    __syncthreads();

    // ---- pass 2: normalize, write attn, PV via MMA ----
    const int wm = wid >> 1, wn = wid & 1;
    const int grp = lane >> 2, tig = lane & 3;
    const int lrow = lane & 15, lcol = (lane >> 4) * 8;

    float acc[2][4][4] = {};

    for (int k0 = 0; k0 < SK_; k0 += 32) {
        // stage P: 128 x 32: read raw s, compute p, write attn, split to smem
        #pragma unroll
        for (int i = 0; i < 4; i++) {
            int c = tid + i * 256;
            int row = c >> 3, off = (c & 7) * 4;
            float mx  = s_mx[row];
            float inv = s_inv[row];
            float* gp = S + (size_t)row * SK_ + k0 + off;
            float4 sv = *(const float4*)gp;
            float4 p;
            p.x = __expf(sv.x - mx) * inv;
            p.y = __expf(sv.y - mx) * inv;
            p.z = __expf(sv.z - mx) * inv;
            p.w = __expf(sv.w - mx) * inv;
            *(float4*)gp = p;                       // final attn probs
            uint32_t h0, l0, h1, l1;
            split2(p.x, p.y, h0, l0);
            split2(p.z, p.w, h1, l1);
            uint32_t* ph = (uint32_t*)(sPh + row * 40 + off);
            uint32_t* pl = (uint32_t*)(sPl + row * 40 + off);
            ph[0] = h0; ph[1] = h1;
            pl[0] = l0; pl[1] = l1;
        }
        // stage V: 32(k) x 64(n) bf16 rows (stride 72 elem = 144 B)
        {
            int row = tid >> 3, off = (tid & 7) * 8;
            size_t g = vbase + (size_t)(k0 + row) * DD + off;
            *(uint4*)&sVh[row * 72 + off] = *(const uint4*)&vh[g];
            *(uint4*)&sVl[row * 72 + off] = *(const uint4*)&vl[g];
        }
        __syncthreads();

        #pragma unroll
        for (int ks = 0; ks < 2; ks++) {
            const int kc = ks * 16 + lcol;
            uint32_t ah[2][4], al[2][4];
            #pragma unroll
            for (int i = 0; i < 2; i++) {
                int r = wm * 32 + i * 16 + lrow;
                ldsm4(ah[i], sh_addr(&sPh[r * 40 + kc]));
                ldsm4(al[i], sh_addr(&sPl[r * 40 + kc]));
            }
            uint32_t bhf[2][4], blf[2][4];
            #pragma unroll
            for (int c = 0; c < 2; c++) {
                int kr = ks * 16 + lrow;
                int nc = wn * 32 + c * 16 + lcol;
                ldsm4t(bhf[c], sh_addr(&sVh[kr * 72 + nc]));
                ldsm4t(blf[c], sh_addr(&sVl[kr * 72 + nc]));
            }
            #pragma unroll
            for (int i = 0; i < 2; i++)
                #pragma unroll
                for (int c = 0; c < 2; c++)
                    #pragma unroll
                    for (int hf = 0; hf < 2; hf++) {
                        uint32_t bH[2] = {bhf[c][hf * 2], bhf[c][hf * 2 + 1]};
                        uint32_t bL[2] = {blf[c][hf * 2], blf[c][hf * 2 + 1]};
                        float* a = acc[i][c * 2 + hf];
                        mma16816(a, ah[i], bH);
                        mma16816(a, ah[i], bL);
                        mma16816(a, al[i], bH);
                    }
        }
        __syncthreads();
    }

    #pragma unroll
    for (int i = 0; i < 2; i++)
        #pragma unroll
        for (int j = 0; j < 4; j++) {
            int r  = m0 + wm * 32 + i * 16 + grp;
            int cN = wn * 32 + j * 8 + tig * 2;
            float* o0 = ctx + (size_t)(b * SQ + r) * DD + h * HD + cN;
            float* o1 = ctx + (size_t)(b * SQ + r + 8) * DD + h * HD + cN;
            o0[0] = acc[i][j][0]; o0[1] = acc[i][j][1];
            o1[0] = acc[i][j][2]; o1[1] = acc[i][j][3];
        }
}

// ---------------------------------------------------------------------------
// out = LayerNorm(q_lin + oproj) * g + b
// ---------------------------------------------------------------------------
__global__ __launch_bounds__(128) void ln_kernel(
    const float* __restrict__ gamma, const float* __restrict__ beta,
    float* __restrict__ out)
{
    __shared__ float sbuf[4];
    const size_t row = blockIdx.x;
    const int tid = threadIdx.x;
    const int lane = tid & 31;
    const int warp = tid >> 5;

    float4 a = ((const float4*)(g_qlin + row * DD))[tid];
    float4 c = ((const float4*)(g_oproj + row * DD))[tid];
    float4 x;
    x.x = a.x + c.x; x.y = a.y + c.y; x.z = a.z + c.z; x.w = a.w + c.w;

    float s = x.x + x.y + x.z + x.w;
    #pragma unroll
    for (int o = 16; o; o >>= 1) s += __shfl_xor_sync(~0u, s, o);
    if (lane == 0) sbuf[warp] = s;
    __syncthreads();
    s = sbuf[0] + sbuf[1] + sbuf[2] + sbuf[3];
    float mu = s * (1.0f / DD);
    __syncthreads();

    float dx = x.x - mu, dy = x.y - mu, dz = x.z - mu, dw = x.w - mu;
    float v = dx * dx + dy * dy + dz * dz + dw * dw;
    #pragma unroll
    for (int o = 16; o; o >>= 1) v += __shfl_xor_sync(~0u, v, o);
    if (lane == 0) sbuf[warp] = v;
    __syncthreads();
    v = sbuf[0] + sbuf[1] + sbuf[2] + sbuf[3];
    float rstd = rsqrtf(v * (1.0f / DD) + EPSLN);

    float4 g4 = ((const float4*)gamma)[tid];
    float4 b4 = ((const float4*)beta)[tid];
    float4 y;
    y.x = dx * rstd * g4.x + b4.x;
    y.y = dy * rstd * g4.y + b4.y;
    y.z = dz * rstd * g4.z + b4.z;
    y.w = dw * rstd * g4.w + b4.w;
    ((float4*)(out + row * DD))[tid] = y;
}

// ---------------------------------------------------------------------------
extern "C" void kernel_launch(void* const* d_in, const int* in_sizes, int n_in,
                              void* d_out, int out_size)
{
    const float* q    = (const float*)d_in[0];
    const float* k    = (const float*)d_in[1];
    const float* v    = (const float*)d_in[2];
    const float* Wq   = (const float*)d_in[3];
    const float* bq   = (const float*)d_in[4];
    const float* Wk   = (const float*)d_in[5];
    const float* bk   = (const float*)d_in[6];
    const float* Wv   = (const float*)d_in[7];
    const float* bv   = (const float*)d_in[8];
    const float* Wo   = (const float*)d_in[9];
    const float* bo   = (const float*)d_in[10];
    const float* ln_g = (const float*)d_in[11];
    const float* ln_b = (const float*)d_in[12];

    float* out  = (float*)d_out;
    float* attn = out + (size_t)LINSZ;

    float *qlin, *ctx, *oproj;
    __nv_bfloat16 *qh, *ql, *kh, *kl, *vh, *vl;
    cudaGetSymbolAddress((void**)&qlin,  g_qlin);
    cudaGetSymbolAddress((void**)&ctx,   g_ctx);
    cudaGetSymbolAddress((void**)&oproj, g_oproj);
    cudaGetSymbolAddress((void**)&qh, g_qh);
    cudaGetSymbolAddress((void**)&ql, g_ql);
    cudaGetSymbolAddress((void**)&kh, g_kh);
    cudaGetSymbolAddress((void**)&kl, g_kl);
    cudaGetSymbolAddress((void**)&vh, g_vh);
    cudaGetSymbolAddress((void**)&vl, g_vl);

    dim3 blk(256);
    dim3 gl(DD / 128, NTOK / 128);               // (4, 64)

    linear_mma<<<gl, blk>>>(q, Wq, bq, qlin, qh, ql, DD, DD);
    linear_mma<<<gl, blk>>>(k, Wk, bk, nullptr, kh, kl, DD, DD);
    linear_mma<<<gl, blk>>>(v, Wv, bv, nullptr, vh, vl, DD, DD);

    scores_mma<<<dim3(SK_ / 128, SQ / 128, B_ * H_), blk>>>(qh, ql, kh, kl, attn);
    smpv_mma<<<dim3(SQ / 128, B_ * H_), blk>>>(attn, vh, vl, ctx);

    linear_mma<<<gl, blk>>>(ctx, Wo, bo, oproj, nullptr, nullptr, DD, DD);
    ln_kernel<<<NTOK, 128>>>(ln_g, ln_b, out);
}

// round 16
// speedup vs baseline: 1.0442x; 1.0442x over previous
#include <cuda_runtime.h>
#include <cuda_bf16.h>
#include <cstdint>

#define B_  4
#define SQ  2048
#define SK_ 2048
#define DD  512
#define H_  8
#define HD  64
#define SCALE 0.125f
#define EPSLN 1e-5f

#define NTOK (B_*SQ)            // 8192
#define LINSZ (NTOK*DD)         // 4194304
#define NROWS (B_*H_*SQ)        // 65536
#define NB    (SK_/128)         // 16

// Scratch (device globals: allocation-free rule)
__device__ float g_qlin[LINSZ];
__device__ float g_ctx[LINSZ];
__device__ float g_oproj[LINSZ];
__device__ __nv_bfloat16 g_qh[LINSZ], g_ql[LINSZ];
__device__ __nv_bfloat16 g_kh[LINSZ], g_kl[LINSZ];
__device__ __nv_bfloat16 g_vh[LINSZ], g_vl[LINSZ];
__device__ float g_pmax[NROWS * NB];
__device__ float g_psum[NROWS * NB];
__device__ float g_mx[NROWS];
__device__ float g_inv[NROWS];

// ---------------------------------------------------------------------------
// Helpers
// ---------------------------------------------------------------------------
__device__ __forceinline__ void split2(float x, float y, uint32_t& hi, uint32_t& lo) {
    __nv_bfloat16 hx = __float2bfloat16(x), hy = __float2bfloat16(y);
    float rx = x - __bfloat162float(hx);
    float ry = y - __bfloat162float(hy);
    __nv_bfloat16 lx = __float2bfloat16(rx), ly = __float2bfloat16(ry);
    hi = ((uint32_t)__bfloat16_as_ushort(hy) << 16) | __bfloat16_as_ushort(hx);
    lo = ((uint32_t)__bfloat16_as_ushort(ly) << 16) | __bfloat16_as_ushort(lx);
}

__device__ __forceinline__ void mma16816(float* c, const uint32_t* a, const uint32_t* b) {
    asm volatile(
        "mma.sync.aligned.m16n8k16.row.col.f32.bf16.bf16.f32 "
        "{%0,%1,%2,%3},{%4,%5,%6,%7},{%8,%9},{%0,%1,%2,%3};\n"
        : "+f"(c[0]), "+f"(c[1]), "+f"(c[2]), "+f"(c[3])
        : "r"(a[0]), "r"(a[1]), "r"(a[2]), "r"(a[3]), "r"(b[0]), "r"(b[1]));
}

__device__ __forceinline__ uint32_t sh_addr(const void* p) {
    return (uint32_t)__cvta_generic_to_shared(p);
}

__device__ __forceinline__ void ldsm4(uint32_t* r, uint32_t addr) {
    asm volatile("ldmatrix.sync.aligned.m8n8.x4.shared.b16 {%0,%1,%2,%3},[%4];\n"
                 : "=r"(r[0]), "=r"(r[1]), "=r"(r[2]), "=r"(r[3]) : "r"(addr) : "memory");
}

__device__ __forceinline__ void ldsm4t(uint32_t* r, uint32_t addr) {
    asm volatile("ldmatrix.sync.aligned.m8n8.x4.trans.shared.b16 {%0,%1,%2,%3},[%4];\n"
                 : "=r"(r[0]), "=r"(r[1]), "=r"(r[2]), "=r"(r[3]) : "r"(addr) : "memory");
}

// ---------------------------------------------------------------------------
// Linear: Y = X @ W^T + bias. fp32 out optional; split-bf16 hi/lo out optional.
// (unchanged from R10 passing kernel)
// ---------------------------------------------------------------------------
__global__ __launch_bounds__(256) void linear_mma(
    const float* __restrict__ X, const float* __restrict__ W,
    const float* __restrict__ bias, float* __restrict__ Y,
    __nv_bfloat16* __restrict__ Yh, __nv_bfloat16* __restrict__ Yl,
    int K, int N)
{
    __shared__ __nv_bfloat16 sAh[128 * 36], sAl[128 * 36];
    __shared__ __nv_bfloat16 sBh[128 * 36], sBl[128 * 36];
    const int m0 = blockIdx.y * 128;
    const int n0 = blockIdx.x * 128;
    const float* A  = X + (size_t)m0 * K;
    const float* Bm = W + (size_t)n0 * K;

    const int tid  = threadIdx.x;
    const int wid  = tid >> 5, lane = tid & 31;
    const int wm   = wid >> 2;
    const int wn   = wid & 3;
    const int grp  = lane >> 2;
    const int tig  = lane & 3;

    float acc[4][4][4] = {};

    for (int k0 = 0; k0 < K; k0 += 32) {
        #pragma unroll
        for (int i = 0; i < 4; i++) {
            int s   = tid + i * 256;
            int row = s >> 3;
            int c   = s & 7;
            float4 av = *(const float4*)(A + (size_t)row * K + k0 + c * 4);
            uint32_t h0, l0, h1, l1;
            split2(av.x, av.y, h0, l0);
            split2(av.z, av.w, h1, l1);
            uint32_t* ph = (uint32_t*)(sAh + row * 36 + c * 4);
            uint32_t* pl = (uint32_t*)(sAl + row * 36 + c * 4);
            ph[0] = h0; ph[1] = h1;
            pl[0] = l0; pl[1] = l1;

            float4 bv = *(const float4*)(Bm + (size_t)row * K + k0 + c * 4);
            split2(bv.x, bv.y, h0, l0);
            split2(bv.z, bv.w, h1, l1);
            ph = (uint32_t*)(sBh + row * 36 + c * 4);
            pl = (uint32_t*)(sBl + row * 36 + c * 4);
            ph[0] = h0; ph[1] = h1;
            pl[0] = l0; pl[1] = l1;
        }
        __syncthreads();

        #pragma unroll
        for (int ks = 0; ks < 2; ks++) {
            const int kb = ks * 16 + tig * 2;
            uint32_t ah[4][4], al[4][4];
            #pragma unroll
            for (int i = 0; i < 4; i++) {
                int r0 = wm * 64 + i * 16 + grp;
                ah[i][0] = *(const uint32_t*)(sAh + r0 * 36 + kb);
                ah[i][1] = *(const uint32_t*)(sAh + (r0 + 8) * 36 + kb);
                ah[i][2] = *(const uint32_t*)(sAh + r0 * 36 + kb + 8);
                ah[i][3] = *(const uint32_t*)(sAh + (r0 + 8) * 36 + kb + 8);
                al[i][0] = *(const uint32_t*)(sAl + r0 * 36 + kb);
                al[i][1] = *(const uint32_t*)(sAl + (r0 + 8) * 36 + kb);
                al[i][2] = *(const uint32_t*)(sAl + r0 * 36 + kb + 8);
                al[i][3] = *(const uint32_t*)(sAl + (r0 + 8) * 36 + kb + 8);
            }
            uint32_t bh[4][2], bl[4][2];
            #pragma unroll
            for (int j = 0; j < 4; j++) {
                int nr = wn * 32 + j * 8 + grp;
                bh[j][0] = *(const uint32_t*)(sBh + nr * 36 + kb);
                bh[j][1] = *(const uint32_t*)(sBh + nr * 36 + kb + 8);
                bl[j][0] = *(const uint32_t*)(sBl + nr * 36 + kb);
                bl[j][1] = *(const uint32_t*)(sBl + nr * 36 + kb + 8);
            }
            #pragma unroll
            for (int i = 0; i < 4; i++)
                #pragma unroll
                for (int j = 0; j < 4; j++) {
                    mma16816(acc[i][j], ah[i], bh[j]);
                    mma16816(acc[i][j], ah[i], bl[j]);
                    mma16816(acc[i][j], al[i], bh[j]);
                }
        }
        __syncthreads();
    }

    #pragma unroll
    for (int i = 0; i < 4; i++) {
        #pragma unroll
        for (int j = 0; j < 4; j++) {
            int r  = m0 + wm * 64 + i * 16 + grp;
            int cN = n0 + wn * 32 + j * 8 + tig * 2;
            float bv0 = bias[cN], bv1 = bias[cN + 1];
            float v00 = acc[i][j][0] + bv0, v01 = acc[i][j][1] + bv1;
            float v10 = acc[i][j][2] + bv0, v11 = acc[i][j][3] + bv1;
            size_t o0 = (size_t)r * N + cN;
            size_t o1 = (size_t)(r + 8) * N + cN;
            if (Y) {
                Y[o0] = v00; Y[o0 + 1] = v01;
                Y[o1] = v10; Y[o1 + 1] = v11;
            }
            if (Yh) {
                uint32_t h0, l0, h1, l1;
                split2(v00, v01, h0, l0);
                split2(v10, v11, h1, l1);
                *(uint32_t*)(Yh + o0) = h0; *(uint32_t*)(Yl + o0) = l0;
                *(uint32_t*)(Yh + o1) = h1; *(uint32_t*)(Yl + o1) = l1;
            }
        }
    }
}

// ---------------------------------------------------------------------------
// scores + per-block row stats: writes raw scaled scores to attn and
// (max, sumexp) over this block's 128 cols to g_pmax/g_psum[row][nb].
// ---------------------------------------------------------------------------
__global__ __launch_bounds__(256, 2) void scores_mma(
    const __nv_bfloat16* __restrict__ qh, const __nv_bfloat16* __restrict__ ql,
    const __nv_bfloat16* __restrict__ kh, const __nv_bfloat16* __restrict__ kl,
    float* __restrict__ attn)
{
    __shared__ __nv_bfloat16 sQh[128 * 40], sQl[128 * 40];
    __shared__ __nv_bfloat16 sKh[128 * 40], sKl[128 * 40];
    __shared__ float s_pm[4][128], s_ps[4][128];
    const int tid = threadIdx.x;
    const int wid = tid >> 5, lane = tid & 31;
    const int bh = blockIdx.z, b = bh >> 3, h = bh & 7;
    const int m0 = blockIdx.y * 128, n0 = blockIdx.x * 128;

    const size_t qbase = (size_t)(b * SQ + m0) * DD + h * HD;
    const size_t kbase = (size_t)(b * SK_ + n0) * DD + h * HD;

    const int wm = wid >> 2, wn = wid & 3;
    const int grp = lane >> 2, tig = lane & 3;
    const int lrow = lane & 15, lcol = (lane >> 4) * 8;

    float acc[4][4][4] = {};

    #pragma unroll
    for (int kh0 = 0; kh0 < HD; kh0 += 32) {
        if (kh0) __syncthreads();
        #pragma unroll
        for (int i = 0; i < 2; i++) {
            int c = tid + i * 256;
            int row = c >> 2, off = (c & 3) * 8;
            size_t g = (size_t)row * DD + kh0 + off;
            *(uint4*)&sQh[row * 40 + off] = *(const uint4*)&qh[qbase + g];
            *(uint4*)&sQl[row * 40 + off] = *(const uint4*)&ql[qbase + g];
            *(uint4*)&sKh[row * 40 + off] = *(const uint4*)&kh[kbase + g];
            *(uint4*)&sKl[row * 40 + off] = *(const uint4*)&kl[kbase + g];
        }
        __syncthreads();

        #pragma unroll
        for (int ks = 0; ks < 2; ks++) {
            const int kc = ks * 16 + lcol;
            uint32_t ah[4][4], al[4][4];
            #pragma unroll
            for (int i = 0; i < 4; i++) {
                int r = wm * 64 + i * 16 + lrow;
                ldsm4(ah[i], sh_addr(&sQh[r * 40 + kc]));
                ldsm4(al[i], sh_addr(&sQl[r * 40 + kc]));
            }
            uint32_t bhf[2][4], blf[2][4];
            #pragma unroll
            for (int c = 0; c < 2; c++) {
                int r = wn * 32 + c * 16 + lrow;
                ldsm4(bhf[c], sh_addr(&sKh[r * 40 + kc]));
                ldsm4(blf[c], sh_addr(&sKl[r * 40 + kc]));
            }
            #pragma unroll
            for (int i = 0; i < 4; i++)
                #pragma unroll
                for (int c = 0; c < 2; c++)
                    #pragma unroll
                    for (int hf = 0; hf < 2; hf++) {
                        uint32_t bH[2] = {bhf[c][hf], bhf[c][hf + 2]};
                        uint32_t bL[2] = {blf[c][hf], blf[c][hf + 2]};
                        float* a = acc[i][c * 2 + hf];
                        mma16816(a, ah[i], bH);
                        mma16816(a, ah[i], bL);
                        mma16816(a, al[i], bH);
                    }
        }
    }

    // scale accumulators once
    #pragma unroll
    for (int i = 0; i < 4; i++)
        #pragma unroll
        for (int j = 0; j < 4; j++)
            #pragma unroll
            for (int e = 0; e < 4; e++)
                acc[i][j][e] *= SCALE;

    // store raw scores
    float* obase = attn + (size_t)bh * SQ * SK_ + (size_t)m0 * SK_ + n0;
    #pragma unroll
    for (int i = 0; i < 4; i++)
        #pragma unroll
        for (int j = 0; j < 4; j++) {
            int r  = wm * 64 + i * 16 + grp;
            int cN = wn * 32 + j * 8 + tig * 2;
            float* o0 = obase + (size_t)r * SK_ + cN;
            float* o1 = obase + (size_t)(r + 8) * SK_ + cN;
            o0[0] = acc[i][j][0]; o0[1] = acc[i][j][1];
            o1[0] = acc[i][j][2]; o1[1] = acc[i][j][3];
        }

    // per-row (max, sumexp) over this block's 128 cols
    #pragma unroll
    for (int i = 0; i < 4; i++) {
        #pragma unroll
        for (int half = 0; half < 2; half++) {
            float m = -1e30f;
            #pragma unroll
            for (int j = 0; j < 4; j++)
                m = fmaxf(m, fmaxf(acc[i][j][half * 2], acc[i][j][half * 2 + 1]));
            float s = 0.0f;
            #pragma unroll
            for (int j = 0; j < 4; j++)
                s += __expf(acc[i][j][half * 2] - m) + __expf(acc[i][j][half * 2 + 1] - m);
            #pragma unroll
            for (int o = 1; o < 4; o <<= 1) {
                float mo = __shfl_xor_sync(~0u, m, o);
                float so = __shfl_xor_sync(~0u, s, o);
                float mn = fmaxf(m, mo);
                s = s * __expf(m - mn) + so * __expf(mo - mn);
                m = mn;
            }
            if (tig == 0) {
                int row = wm * 64 + i * 16 + half * 8 + grp;
                s_pm[wn][row] = m;
                s_ps[wn][row] = s;
            }
        }
    }
    __syncthreads();
    if (tid < 128) {
        float m = s_pm[0][tid], s = s_ps[0][tid];
        #pragma unroll
        for (int w = 1; w < 4; w++) {
            float mo = s_pm[w][tid], so = s_ps[w][tid];
            float mn = fmaxf(m, mo);
            s = s * __expf(m - mn) + so * __expf(mo - mn);
            m = mn;
        }
        size_t idx = ((size_t)bh * SQ + m0 + tid) * NB + blockIdx.x;
        g_pmax[idx] = m;
        g_psum[idx] = s;
    }
}

// ---------------------------------------------------------------------------
// Merge partial row stats -> g_mx, g_inv. One thread per row.
// ---------------------------------------------------------------------------
__global__ __launch_bounds__(256) void rowstats_kernel()
{
    int row = blockIdx.x * 256 + threadIdx.x;
    const float* pm = g_pmax + (size_t)row * NB;
    const float* ps = g_psum + (size_t)row * NB;
    float m = -1e30f;
    #pragma unroll
    for (int i = 0; i < NB; i++) m = fmaxf(m, pm[i]);
    float s = 0.0f;
    #pragma unroll
    for (int i = 0; i < NB; i++) s += ps[i] * __expf(pm[i] - m);
    g_mx[row]  = m;
    g_inv[row] = 1.0f / s;
}

// ---------------------------------------------------------------------------
// Fused normalize + attn write + PV. Reads raw S once, p = exp(s-mx)*inv,
// writes final probs in place, split-bf16 to smem, MMA with V.
// ---------------------------------------------------------------------------
__global__ __launch_bounds__(256, 2) void pv_mma(
    float* __restrict__ attn,
    const __nv_bfloat16* __restrict__ vh, const __nv_bfloat16* __restrict__ vl,
    float* __restrict__ ctx)
{
    __shared__ __nv_bfloat16 sPh[128 * 40], sPl[128 * 40];
    __shared__ __nv_bfloat16 sVh[32 * 72],  sVl[32 * 72];
    __shared__ float s_mx[128], s_inv[128];

    const int tid = threadIdx.x;
    const int wid = tid >> 5, lane = tid & 31;
    const int wm = wid >> 1, wn = wid & 1;
    const int grp = lane >> 2, tig = lane & 3;
    const int lrow = lane & 15, lcol = (lane >> 4) * 8;
    const int bh = blockIdx.y, b = bh >> 3, h = bh & 7;
    const int m0 = blockIdx.x * 128;

    float* S = attn + (size_t)bh * SQ * SK_ + (size_t)m0 * SK_;
    const size_t vbase = (size_t)b * SK_ * DD + h * HD;

    if (tid < 128) {
        size_t ridx = (size_t)bh * SQ + m0 + tid;
        s_mx[tid]  = g_mx[ridx];
        s_inv[tid] = g_inv[ridx];
    }
    __syncthreads();

    float acc[2][4][4] = {};

    for (int k0 = 0; k0 < SK_; k0 += 32) {
        // stage P: read raw s, p = exp(s-mx)*inv, write attn, split to smem
        #pragma unroll
        for (int i = 0; i < 4; i++) {
            int c = tid + i * 256;
            int row = c >> 3, off = (c & 7) * 4;
            float mx  = s_mx[row];
            float inv = s_inv[row];
            float* gp = S + (size_t)row * SK_ + k0 + off;
            float4 sv = *(const float4*)gp;
            float4 p;
            p.x = __expf(sv.x - mx) * inv;
            p.y = __expf(sv.y - mx) * inv;
            p.z = __expf(sv.z - mx) * inv;
            p.w = __expf(sv.w - mx) * inv;
            *(float4*)gp = p;                       // final attn probs
            uint32_t h0, l0, h1, l1;
            split2(p.x, p.y, h0, l0);
            split2(p.z, p.w, h1, l1);
            uint32_t* ph = (uint32_t*)(sPh + row * 40 + off);
            uint32_t* pl = (uint32_t*)(sPl + row * 40 + off);
            ph[0] = h0; ph[1] = h1;
            pl[0] = l0; pl[1] = l1;
        }
        // stage V: 32(k) x 64(n) bf16 rows (stride 72 elem = 144 B)
        {
            int row = tid >> 3, off = (tid & 7) * 8;
            size_t g = vbase + (size_t)(k0 + row) * DD + off;
            *(uint4*)&sVh[row * 72 + off] = *(const uint4*)&vh[g];
            *(uint4*)&sVl[row * 72 + off] = *(const uint4*)&vl[g];
        }
        __syncthreads();

        #pragma unroll
        for (int ks = 0; ks < 2; ks++) {
            const int kc = ks * 16 + lcol;
            uint32_t ah[2][4], al[2][4];
            #pragma unroll
            for (int i = 0; i < 2; i++) {
                int r = wm * 32 + i * 16 + lrow;
                ldsm4(ah[i], sh_addr(&sPh[r * 40 + kc]));
                ldsm4(al[i], sh_addr(&sPl[r * 40 + kc]));
            }
            uint32_t bhf[2][4], blf[2][4];
            #pragma unroll
            for (int c = 0; c < 2; c++) {
                int kr = ks * 16 + lrow;
                int nc = wn * 32 + c * 16 + lcol;
                ldsm4t(bhf[c], sh_addr(&sVh[kr * 72 + nc]));
                ldsm4t(blf[c], sh_addr(&sVl[kr * 72 + nc]));
            }
            #pragma unroll
            for (int i = 0; i < 2; i++)
                #pragma unroll
                for (int c = 0; c < 2; c++)
                    #pragma unroll
                    for (int hf = 0; hf < 2; hf++) {
                        uint32_t bH[2] = {bhf[c][hf * 2], bhf[c][hf * 2 + 1]};
                        uint32_t bL[2] = {blf[c][hf * 2], blf[c][hf * 2 + 1]};
                        float* a = acc[i][c * 2 + hf];
                        mma16816(a, ah[i], bH);
                        mma16816(a, ah[i], bL);
                        mma16816(a, al[i], bH);
                    }
        }
        __syncthreads();
    }

    #pragma unroll
    for (int i = 0; i < 2; i++)
        #pragma unroll
        for (int j = 0; j < 4; j++) {
            int r  = m0 + wm * 32 + i * 16 + grp;
            int cN = wn * 32 + j * 8 + tig * 2;
            float* o0 = ctx + (size_t)(b * SQ + r) * DD + h * HD + cN;
            float* o1 = ctx + (size_t)(b * SQ + r + 8) * DD + h * HD + cN;
            o0[0] = acc[i][j][0]; o0[1] = acc[i][j][1];
            o1[0] = acc[i][j][2]; o1[1] = acc[i][j][3];
        }
}

// ---------------------------------------------------------------------------
// out = LayerNorm(q_lin + oproj) * g + b
// ---------------------------------------------------------------------------
__global__ __launch_bounds__(128) void ln_kernel(
    const float* __restrict__ gamma, const float* __restrict__ beta,
    float* __restrict__ out)
{
    __shared__ float sbuf[4];
    const size_t row = blockIdx.x;
    const int tid = threadIdx.x;
    const int lane = tid & 31;
    const int warp = tid >> 5;

    float4 a = ((const float4*)(g_qlin + row * DD))[tid];
    float4 c = ((const float4*)(g_oproj + row * DD))[tid];
    float4 x;
    x.x = a.x + c.x; x.y = a.y + c.y; x.z = a.z + c.z; x.w = a.w + c.w;

    float s = x.x + x.y + x.z + x.w;
    #pragma unroll
    for (int o = 16; o; o >>= 1) s += __shfl_xor_sync(~0u, s, o);
    if (lane == 0) sbuf[warp] = s;
    __syncthreads();
    s = sbuf[0] + sbuf[1] + sbuf[2] + sbuf[3];
    float mu = s * (1.0f / DD);
    __syncthreads();

    float dx = x.x - mu, dy = x.y - mu, dz = x.z - mu, dw = x.w - mu;
    float v = dx * dx + dy * dy + dz * dz + dw * dw;
    #pragma unroll
    for (int o = 16; o; o >>= 1) v += __shfl_xor_sync(~0u, v, o);
    if (lane == 0) sbuf[warp] = v;
    __syncthreads();
    v = sbuf[0] + sbuf[1] + sbuf[2] + sbuf[3];
    float rstd = rsqrtf(v * (1.0f / DD) + EPSLN);

    float4 g4 = ((const float4*)gamma)[tid];
    float4 b4 = ((const float4*)beta)[tid];
    float4 y;
    y.x = dx * rstd * g4.x + b4.x;
    y.y = dy * rstd * g4.y + b4.y;
    y.z = dz * rstd * g4.z + b4.z;
    y.w = dw * rstd * g4.w + b4.w;
    ((float4*)(out + row * DD))[tid] = y;
}

// ---------------------------------------------------------------------------
extern "C" void kernel_launch(void* const* d_in, const int* in_sizes, int n_in,
                              void* d_out, int out_size)
{
    const float* q    = (const float*)d_in[0];
    const float* k    = (const float*)d_in[1];
    const float* v    = (const float*)d_in[2];
    const float* Wq   = (const float*)d_in[3];
    const float* bq   = (const float*)d_in[4];
    const float* Wk   = (const float*)d_in[5];
    const float* bk   = (const float*)d_in[6];
    const float* Wv   = (const float*)d_in[7];
    const float* bv   = (const float*)d_in[8];
    const float* Wo   = (const float*)d_in[9];
    const float* bo   = (const float*)d_in[10];
    const float* ln_g = (const float*)d_in[11];
    const float* ln_b = (const float*)d_in[12];

    float* out  = (float*)d_out;
    float* attn = out + (size_t)LINSZ;

    float *qlin, *ctx, *oproj;
    __nv_bfloat16 *qh, *ql, *kh, *kl, *vh, *vl;
    cudaGetSymbolAddress((void**)&qlin,  g_qlin);
    cudaGetSymbolAddress((void**)&ctx,   g_ctx);
    cudaGetSymbolAddress((void**)&oproj, g_oproj);
    cudaGetSymbolAddress((void**)&qh, g_qh);
    cudaGetSymbolAddress((void**)&ql, g_ql);
    cudaGetSymbolAddress((void**)&kh, g_kh);
    cudaGetSymbolAddress((void**)&kl, g_kl);
    cudaGetSymbolAddress((void**)&vh, g_vh);
    cudaGetSymbolAddress((void**)&vl, g_vl);

    dim3 blk(256);
    dim3 gl(DD / 128, NTOK / 128);               // (4, 64)

    linear_mma<<<gl, blk>>>(q, Wq, bq, qlin, qh, ql, DD, DD);
    linear_mma<<<gl, blk>>>(k, Wk, bk, nullptr, kh, kl, DD, DD);
    linear_mma<<<gl, blk>>>(v, Wv, bv, nullptr, vh, vl, DD, DD);

    scores_mma<<<dim3(SK_ / 128, SQ / 128, B_ * H_), blk>>>(qh, ql, kh, kl, attn);
    rowstats_kernel<<<NROWS / 256, 256>>>();
    pv_mma<<<dim3(SQ / 128, B_ * H_), blk>>>(attn, vh, vl, ctx);

    linear_mma<<<gl, blk>>>(ctx, Wo, bo, oproj, nullptr, nullptr, DD, DD);
    ln_kernel<<<NTOK, 128>>>(ln_g, ln_b, out);
}

// round 17
// speedup vs baseline: 1.2904x; 1.2358x over previous
#include <cuda_runtime.h>
#include <cuda_bf16.h>
#include <cstdint>

#define B_  4
#define SQ  2048
#define SK_ 2048
#define DD  512
#define H_  8
#define HD  64
#define SCALE 0.125f
#define EPSLN 1e-5f

#define NTOK (B_*SQ)            // 8192
#define LINSZ (NTOK*DD)         // 4194304

// Scratch (device globals: allocation-free rule)
__device__ float g_qlin[LINSZ];
__device__ float g_ctx[LINSZ];
__device__ float g_oproj[LINSZ];
__device__ __nv_bfloat16 g_qh[LINSZ], g_ql[LINSZ];
__device__ __nv_bfloat16 g_kh[LINSZ], g_kl[LINSZ];
__device__ __nv_bfloat16 g_vh[LINSZ], g_vl[LINSZ];

// ---------------------------------------------------------------------------
// Helpers
// ---------------------------------------------------------------------------
__device__ __forceinline__ void split2(float x, float y, uint32_t& hi, uint32_t& lo) {
    __nv_bfloat16 hx = __float2bfloat16(x), hy = __float2bfloat16(y);
    float rx = x - __bfloat162float(hx);
    float ry = y - __bfloat162float(hy);
    __nv_bfloat16 lx = __float2bfloat16(rx), ly = __float2bfloat16(ry);
    hi = ((uint32_t)__bfloat16_as_ushort(hy) << 16) | __bfloat16_as_ushort(hx);
    lo = ((uint32_t)__bfloat16_as_ushort(ly) << 16) | __bfloat16_as_ushort(lx);
}

__device__ __forceinline__ void mma16816(float* c, const uint32_t* a, const uint32_t* b) {
    asm volatile(
        "mma.sync.aligned.m16n8k16.row.col.f32.bf16.bf16.f32 "
        "{%0,%1,%2,%3},{%4,%5,%6,%7},{%8,%9},{%0,%1,%2,%3};\n"
        : "+f"(c[0]), "+f"(c[1]), "+f"(c[2]), "+f"(c[3])
        : "r"(a[0]), "r"(a[1]), "r"(a[2]), "r"(a[3]), "r"(b[0]), "r"(b[1]));
}

__device__ __forceinline__ uint32_t sh_addr(const void* p) {
    return (uint32_t)__cvta_generic_to_shared(p);
}

__device__ __forceinline__ void ldsm4(uint32_t* r, uint32_t addr) {
    asm volatile("ldmatrix.sync.aligned.m8n8.x4.shared.b16 {%0,%1,%2,%3},[%4];\n"
                 : "=r"(r[0]), "=r"(r[1]), "=r"(r[2]), "=r"(r[3]) : "r"(addr) : "memory");
}

__device__ __forceinline__ void ldsm4t(uint32_t* r, uint32_t addr) {
    asm volatile("ldmatrix.sync.aligned.m8n8.x4.trans.shared.b16 {%0,%1,%2,%3},[%4];\n"
                 : "=r"(r[0]), "=r"(r[1]), "=r"(r[2]), "=r"(r[3]) : "r"(addr) : "memory");
}

// ---------------------------------------------------------------------------
// Linear: Y = X @ W^T + bias. fp32 out optional; split-bf16 hi/lo out optional.
// (unchanged from R10 passing kernel)
// ---------------------------------------------------------------------------
__global__ __launch_bounds__(256) void linear_mma(
    const float* __restrict__ X, const float* __restrict__ W,
    const float* __restrict__ bias, float* __restrict__ Y,
    __nv_bfloat16* __restrict__ Yh, __nv_bfloat16* __restrict__ Yl,
    int K, int N)
{
    __shared__ __nv_bfloat16 sAh[128 * 36], sAl[128 * 36];
    __shared__ __nv_bfloat16 sBh[128 * 36], sBl[128 * 36];
    const int m0 = blockIdx.y * 128;
    const int n0 = blockIdx.x * 128;
    const float* A  = X + (size_t)m0 * K;
    const float* Bm = W + (size_t)n0 * K;

    const int tid  = threadIdx.x;
    const int wid  = tid >> 5, lane = tid & 31;
    const int wm   = wid >> 2;
    const int wn   = wid & 3;
    const int grp  = lane >> 2;
    const int tig  = lane & 3;

    float acc[4][4][4] = {};

    for (int k0 = 0; k0 < K; k0 += 32) {
        #pragma unroll
        for (int i = 0; i < 4; i++) {
            int s   = tid + i * 256;
            int row = s >> 3;
            int c   = s & 7;
            float4 av = *(const float4*)(A + (size_t)row * K + k0 + c * 4);
            uint32_t h0, l0, h1, l1;
            split2(av.x, av.y, h0, l0);
            split2(av.z, av.w, h1, l1);
            uint32_t* ph = (uint32_t*)(sAh + row * 36 + c * 4);
            uint32_t* pl = (uint32_t*)(sAl + row * 36 + c * 4);
            ph[0] = h0; ph[1] = h1;
            pl[0] = l0; pl[1] = l1;

            float4 bv = *(const float4*)(Bm + (size_t)row * K + k0 + c * 4);
            split2(bv.x, bv.y, h0, l0);
            split2(bv.z, bv.w, h1, l1);
            ph = (uint32_t*)(sBh + row * 36 + c * 4);
            pl = (uint32_t*)(sBl + row * 36 + c * 4);
            ph[0] = h0; ph[1] = h1;
            pl[0] = l0; pl[1] = l1;
        }
        __syncthreads();

        #pragma unroll
        for (int ks = 0; ks < 2; ks++) {
            const int kb = ks * 16 + tig * 2;
            uint32_t ah[4][4], al[4][4];
            #pragma unroll
            for (int i = 0; i < 4; i++) {
                int r0 = wm * 64 + i * 16 + grp;
                ah[i][0] = *(const uint32_t*)(sAh + r0 * 36 + kb);
                ah[i][1] = *(const uint32_t*)(sAh + (r0 + 8) * 36 + kb);
                ah[i][2] = *(const uint32_t*)(sAh + r0 * 36 + kb + 8);
                ah[i][3] = *(const uint32_t*)(sAh + (r0 + 8) * 36 + kb + 8);
                al[i][0] = *(const uint32_t*)(sAl + r0 * 36 + kb);
                al[i][1] = *(const uint32_t*)(sAl + (r0 + 8) * 36 + kb);
                al[i][2] = *(const uint32_t*)(sAl + r0 * 36 + kb + 8);
                al[i][3] = *(const uint32_t*)(sAl + (r0 + 8) * 36 + kb + 8);
            }
            uint32_t bh[4][2], bl[4][2];
            #pragma unroll
            for (int j = 0; j < 4; j++) {
                int nr = wn * 32 + j * 8 + grp;
                bh[j][0] = *(const uint32_t*)(sBh + nr * 36 + kb);
                bh[j][1] = *(const uint32_t*)(sBh + nr * 36 + kb + 8);
                bl[j][0] = *(const uint32_t*)(sBl + nr * 36 + kb);
                bl[j][1] = *(const uint32_t*)(sBl + nr * 36 + kb + 8);
            }
            #pragma unroll
            for (int i = 0; i < 4; i++)
                #pragma unroll
                for (int j = 0; j < 4; j++) {
                    mma16816(acc[i][j], ah[i], bh[j]);
                    mma16816(acc[i][j], ah[i], bl[j]);
                    mma16816(acc[i][j], al[i], bh[j]);
                }
        }
        __syncthreads();
    }

    #pragma unroll
    for (int i = 0; i < 4; i++) {
        #pragma unroll
        for (int j = 0; j < 4; j++) {
            int r  = m0 + wm * 64 + i * 16 + grp;
            int cN = n0 + wn * 32 + j * 8 + tig * 2;
            float bv0 = bias[cN], bv1 = bias[cN + 1];
            float v00 = acc[i][j][0] + bv0, v01 = acc[i][j][1] + bv1;
            float v10 = acc[i][j][2] + bv0, v11 = acc[i][j][3] + bv1;
            size_t o0 = (size_t)r * N + cN;
            size_t o1 = (size_t)(r + 8) * N + cN;
            if (Y) {
                Y[o0] = v00; Y[o0 + 1] = v01;
                Y[o1] = v10; Y[o1 + 1] = v11;
            }
            if (Yh) {
                uint32_t h0, l0, h1, l1;
                split2(v00, v01, h0, l0);
                split2(v10, v11, h1, l1);
                *(uint32_t*)(Yh + o0) = h0; *(uint32_t*)(Yl + o0) = l0;
                *(uint32_t*)(Yh + o1) = h1; *(uint32_t*)(Yl + o1) = l1;
            }
        }
    }
}

// ---------------------------------------------------------------------------
// scores[b,h,q,k] = SCALE * qh . kh   (per bh: M=N=2048, K=64)
// R10 mainloop + NEW coalesced epilogue: accumulators staged through smem
// (aliased over the dead Q/K tiles) and written as full float4 rows.
// ---------------------------------------------------------------------------
__global__ __launch_bounds__(256, 2) void scores_mma(
    const __nv_bfloat16* __restrict__ qh, const __nv_bfloat16* __restrict__ ql,
    const __nv_bfloat16* __restrict__ kh, const __nv_bfloat16* __restrict__ kl,
    float* __restrict__ attn)
{
    __shared__ __align__(16) char smem_raw[4 * 128 * 40 * sizeof(__nv_bfloat16)];
    __nv_bfloat16* sQh = (__nv_bfloat16*)smem_raw;
    __nv_bfloat16* sQl = sQh + 128 * 40;
    __nv_bfloat16* sKh = sQl + 128 * 40;
    __nv_bfloat16* sKl = sKh + 128 * 40;

    const int tid = threadIdx.x;
    const int wid = tid >> 5, lane = tid & 31;
    const int bh = blockIdx.z, b = bh >> 3, h = bh & 7;
    const int m0 = blockIdx.y * 128, n0 = blockIdx.x * 128;

    const size_t qbase = (size_t)(b * SQ + m0) * DD + h * HD;
    const size_t kbase = (size_t)(b * SK_ + n0) * DD + h * HD;

    const int wm = wid >> 2, wn = wid & 3;
    const int grp = lane >> 2, tig = lane & 3;
    const int lrow = lane & 15, lcol = (lane >> 4) * 8;

    float acc[4][4][4] = {};

    #pragma unroll
    for (int kh0 = 0; kh0 < HD; kh0 += 32) {
        if (kh0) __syncthreads();
        #pragma unroll
        for (int i = 0; i < 2; i++) {
            int c = tid + i * 256;
            int row = c >> 2, off = (c & 3) * 8;
            size_t g = (size_t)row * DD + kh0 + off;
            *(uint4*)&sQh[row * 40 + off] = *(const uint4*)&qh[qbase + g];
            *(uint4*)&sQl[row * 40 + off] = *(const uint4*)&ql[qbase + g];
            *(uint4*)&sKh[row * 40 + off] = *(const uint4*)&kh[kbase + g];
            *(uint4*)&sKl[row * 40 + off] = *(const uint4*)&kl[kbase + g];
        }
        __syncthreads();

        #pragma unroll
        for (int ks = 0; ks < 2; ks++) {
            const int kc = ks * 16 + lcol;
            uint32_t ah[4][4], al[4][4];
            #pragma unroll
            for (int i = 0; i < 4; i++) {
                int r = wm * 64 + i * 16 + lrow;
                ldsm4(ah[i], sh_addr(&sQh[r * 40 + kc]));
                ldsm4(al[i], sh_addr(&sQl[r * 40 + kc]));
            }
            uint32_t bhf[2][4], blf[2][4];
            #pragma unroll
            for (int c = 0; c < 2; c++) {
                int r = wn * 32 + c * 16 + lrow;
                ldsm4(bhf[c], sh_addr(&sKh[r * 40 + kc]));
                ldsm4(blf[c], sh_addr(&sKl[r * 40 + kc]));
            }
            #pragma unroll
            for (int i = 0; i < 4; i++)
                #pragma unroll
                for (int c = 0; c < 2; c++)
                    #pragma unroll
                    for (int hf = 0; hf < 2; hf++) {
                        uint32_t bH[2] = {bhf[c][hf], bhf[c][hf + 2]};
                        uint32_t bL[2] = {blf[c][hf], blf[c][hf + 2]};
                        float* a = acc[i][c * 2 + hf];
                        mma16816(a, ah[i], bH);
                        mma16816(a, ah[i], bL);
                        mma16816(a, al[i], bH);
                    }
        }
    }

    // ---- coalesced epilogue: stage 32x128 chunks in smem, write float4 ----
    float* sOut = (float*)smem_raw;                 // 32*132 floats = 16.9 KB
    float* obase = attn + (size_t)bh * SQ * SK_ + (size_t)m0 * SK_ + n0;
    #pragma unroll
    for (int i = 0; i < 4; i++) {
        __syncthreads();    // tiles (i=0) / previous copy (i>0) done
        #pragma unroll
        for (int j = 0; j < 4; j++)
            #pragma unroll
            for (int half = 0; half < 2; half++) {
                int lr = wm * 16 + half * 8 + grp;
                int cN = wn * 32 + j * 8 + tig * 2;
                sOut[lr * 132 + cN]     = acc[i][j][half * 2]     * SCALE;
                sOut[lr * 132 + cN + 1] = acc[i][j][half * 2 + 1] * SCALE;
            }
        __syncthreads();
        #pragma unroll
        for (int it = 0; it < 4; it++) {
            int slot = tid + it * 256;              // 0..1023
            int lr = slot >> 5, c4 = slot & 31;
            int grow = (lr < 16) ? (i * 16 + lr) : (64 + i * 16 + lr - 16);
            float4 vv = *(float4*)&sOut[lr * 132 + c4 * 4];
            *(float4*)(obase + (size_t)grow * SK_ + c4 * 4) = vv;
        }
    }
}

// ---------------------------------------------------------------------------
// In-place row softmax over SK=2048.  (R10 version)
// ---------------------------------------------------------------------------
__global__ __launch_bounds__(256) void softmax_kernel(float* __restrict__ attn)
{
    __shared__ float sbuf[8];
    const size_t row = blockIdx.x;
    float* p = attn + row * (size_t)SK_;
    const int tid = threadIdx.x;
    const int lane = tid & 31;
    const int warp = tid >> 5;

    float4 v0 = ((const float4*)p)[tid];
    float4 v1 = ((const float4*)p)[tid + 256];

    float mx = fmaxf(fmaxf(fmaxf(v0.x, v0.y), fmaxf(v0.z, v0.w)),
                     fmaxf(fmaxf(v1.x, v1.y), fmaxf(v1.z, v1.w)));
    #pragma unroll
    for (int o = 16; o; o >>= 1) mx = fmaxf(mx, __shfl_xor_sync(~0u, mx, o));
    if (lane == 0) sbuf[warp] = mx;
    __syncthreads();
    mx = sbuf[0];
    #pragma unroll
    for (int i = 1; i < 8; i++) mx = fmaxf(mx, sbuf[i]);
    __syncthreads();

    v0.x = expf(v0.x - mx); v0.y = expf(v0.y - mx);
    v0.z = expf(v0.z - mx); v0.w = expf(v0.w - mx);
    v1.x = expf(v1.x - mx); v1.y = expf(v1.y - mx);
    v1.z = expf(v1.z - mx); v1.w = expf(v1.w - mx);

    float s = v0.x + v0.y + v0.z + v0.w + v1.x + v1.y + v1.z + v1.w;
    #pragma unroll
    for (int o = 16; o; o >>= 1) s += __shfl_xor_sync(~0u, s, o);
    if (lane == 0) sbuf[warp] = s;
    __syncthreads();
    s = sbuf[0];
    #pragma unroll
    for (int i = 1; i < 8; i++) s += sbuf[i];

    float inv = 1.0f / s;
    v0.x *= inv; v0.y *= inv; v0.z *= inv; v0.w *= inv;
    v1.x *= inv; v1.y *= inv; v1.z *= inv; v1.w *= inv;
    ((float4*)p)[tid] = v0;
    ((float4*)p)[tid + 256] = v1;
}

// ---------------------------------------------------------------------------
// ctx = P @ V  (per bh: M=2048, N=64, K=2048), BK=32.  (R10 version)
// ---------------------------------------------------------------------------
__global__ __launch_bounds__(256, 2) void pv_mma(
    const float* __restrict__ attn,
    const __nv_bfloat16* __restrict__ vh, const __nv_bfloat16* __restrict__ vl,
    float* __restrict__ ctx)
{
    __shared__ __nv_bfloat16 sPh[128 * 40], sPl[128 * 40];
    __shared__ __nv_bfloat16 sVh[32 * 72],  sVl[32 * 72];
    const int tid = threadIdx.x;
    const int wid = tid >> 5, lane = tid & 31;
    const int wm = wid >> 1, wn = wid & 1;
    const int grp = lane >> 2, tig = lane & 3;
    const int lrow = lane & 15, lcol = (lane >> 4) * 8;
    const int bh = blockIdx.y, b = bh >> 3, h = bh & 7;
    const int m0 = blockIdx.x * 128;

    const float* P = attn + (size_t)bh * SQ * SK_ + (size_t)m0 * SK_;
    const size_t vbase = (size_t)b * SK_ * DD + h * HD;

    float acc[2][4][4] = {};

    for (int k0 = 0; k0 < SK_; k0 += 32) {
        #pragma unroll
        for (int i = 0; i < 4; i++) {
            int c = tid + i * 256;
            int row = c >> 3, off = (c & 7) * 4;
            float4 pv = *(const float4*)(P + (size_t)row * SK_ + k0 + off);
            uint32_t h0, l0, h1, l1;
            split2(pv.x, pv.y, h0, l0);
            split2(pv.z, pv.w, h1, l1);
            uint32_t* ph = (uint32_t*)(sPh + row * 40 + off);
            uint32_t* pl = (uint32_t*)(sPl + row * 40 + off);
            ph[0] = h0; ph[1] = h1;
            pl[0] = l0; pl[1] = l1;
        }
        {
            int row = tid >> 3, off = (tid & 7) * 8;
            size_t g = vbase + (size_t)(k0 + row) * DD + off;
            *(uint4*)&sVh[row * 72 + off] = *(const uint4*)&vh[g];
            *(uint4*)&sVl[row * 72 + off] = *(const uint4*)&vl[g];
        }
        __syncthreads();

        #pragma unroll
        for (int ks = 0; ks < 2; ks++) {
            const int kc = ks * 16 + lcol;
            uint32_t ah[2][4], al[2][4];
            #pragma unroll
            for (int i = 0; i < 2; i++) {
                int r = wm * 32 + i * 16 + lrow;
                ldsm4(ah[i], sh_addr(&sPh[r * 40 + kc]));
                ldsm4(al[i], sh_addr(&sPl[r * 40 + kc]));
            }
            uint32_t bhf[2][4], blf[2][4];
            #pragma unroll
            for (int c = 0; c < 2; c++) {
                int kr = ks * 16 + lrow;
                int nc = wn * 32 + c * 16 + lcol;
                ldsm4t(bhf[c], sh_addr(&sVh[kr * 72 + nc]));
                ldsm4t(blf[c], sh_addr(&sVl[kr * 72 + nc]));
            }
            #pragma unroll
            for (int i = 0; i < 2; i++)
                #pragma unroll
                for (int c = 0; c < 2; c++)
                    #pragma unroll
                    for (int hf = 0; hf < 2; hf++) {
                        uint32_t bH[2] = {bhf[c][hf * 2], bhf[c][hf * 2 + 1]};
                        uint32_t bL[2] = {blf[c][hf * 2], blf[c][hf * 2 + 1]};
                        float* a = acc[i][c * 2 + hf];
                        mma16816(a, ah[i], bH);
                        mma16816(a, ah[i], bL);
                        mma16816(a, al[i], bH);
                    }
        }
        __syncthreads();
    }

    #pragma unroll
    for (int i = 0; i < 2; i++)
        #pragma unroll
        for (int j = 0; j < 4; j++) {
            int r  = m0 + wm * 32 + i * 16 + grp;
            int cN = wn * 32 + j * 8 + tig * 2;
            float* o0 = ctx + (size_t)(b * SQ + r) * DD + h * HD + cN;
            float* o1 = ctx + (size_t)(b * SQ + r + 8) * DD + h * HD + cN;
            o0[0] = acc[i][j][0]; o0[1] = acc[i][j][1];
            o1[0] = acc[i][j][2]; o1[1] = acc[i][j][3];
        }
}

// ---------------------------------------------------------------------------
// out = LayerNorm(q_lin + oproj) * g + b
// ---------------------------------------------------------------------------
__global__ __launch_bounds__(128) void ln_kernel(
    const float* __restrict__ gamma, const float* __restrict__ beta,
    float* __restrict__ out)
{
    __shared__ float sbuf[4];
    const size_t row = blockIdx.x;
    const int tid = threadIdx.x;
    const int lane = tid & 31;
    const int warp = tid >> 5;

    float4 a = ((const float4*)(g_qlin + row * DD))[tid];
    float4 c = ((const float4*)(g_oproj + row * DD))[tid];
    float4 x;
    x.x = a.x + c.x; x.y = a.y + c.y; x.z = a.z + c.z; x.w = a.w + c.w;

    float s = x.x + x.y + x.z + x.w;
    #pragma unroll
    for (int o = 16; o; o >>= 1) s += __shfl_xor_sync(~0u, s, o);
    if (lane == 0) sbuf[warp] = s;
    __syncthreads();
    s = sbuf[0] + sbuf[1] + sbuf[2] + sbuf[3];
    float mu = s * (1.0f / DD);
    __syncthreads();

    float dx = x.x - mu, dy = x.y - mu, dz = x.z - mu, dw = x.w - mu;
    float v = dx * dx + dy * dy + dz * dz + dw * dw;
    #pragma unroll
    for (int o = 16; o; o >>= 1) v += __shfl_xor_sync(~0u, v, o);
    if (lane == 0) sbuf[warp] = v;
    __syncthreads();
    v = sbuf[0] + sbuf[1] + sbuf[2] + sbuf[3];
    float rstd = rsqrtf(v * (1.0f / DD) + EPSLN);

    float4 g4 = ((const float4*)gamma)[tid];
    float4 b4 = ((const float4*)beta)[tid];
    float4 y;
    y.x = dx * rstd * g4.x + b4.x;
    y.y = dy * rstd * g4.y + b4.y;
    y.z = dz * rstd * g4.z + b4.z;
    y.w = dw * rstd * g4.w + b4.w;
    ((float4*)(out + row * DD))[tid] = y;
}

// ---------------------------------------------------------------------------
extern "C" void kernel_launch(void* const* d_in, const int* in_sizes, int n_in,
                              void* d_out, int out_size)
{
    const float* q    = (const float*)d_in[0];
    const float* k    = (const float*)d_in[1];
    const float* v    = (const float*)d_in[2];
    const float* Wq   = (const float*)d_in[3];
    const float* bq   = (const float*)d_in[4];
    const float* Wk   = (const float*)d_in[5];
    const float* bk   = (const float*)d_in[6];
    const float* Wv   = (const float*)d_in[7];
    const float* bv   = (const float*)d_in[8];
    const float* Wo   = (const float*)d_in[9];
    const float* bo   = (const float*)d_in[10];
    const float* ln_g = (const float*)d_in[11];
    const float* ln_b = (const float*)d_in[12];

    float* out  = (float*)d_out;
    float* attn = out + (size_t)LINSZ;

    float *qlin, *ctx, *oproj;
    __nv_bfloat16 *qh, *ql, *kh, *kl, *vh, *vl;
    cudaGetSymbolAddress((void**)&qlin,  g_qlin);
    cudaGetSymbolAddress((void**)&ctx,   g_ctx);
    cudaGetSymbolAddress((void**)&oproj, g_oproj);
    cudaGetSymbolAddress((void**)&qh, g_qh);
    cudaGetSymbolAddress((void**)&ql, g_ql);
    cudaGetSymbolAddress((void**)&kh, g_kh);
    cudaGetSymbolAddress((void**)&kl, g_kl);
    cudaGetSymbolAddress((void**)&vh, g_vh);
    cudaGetSymbolAddress((void**)&vl, g_vl);

    dim3 blk(256);
    dim3 gl(DD / 128, NTOK / 128);               // (4, 64)

    linear_mma<<<gl, blk>>>(q, Wq, bq, qlin, qh, ql, DD, DD);
    linear_mma<<<gl, blk>>>(k, Wk, bk, nullptr, kh, kl, DD, DD);
    linear_mma<<<gl, blk>>>(v, Wv, bv, nullptr, vh, vl, DD, DD);

    scores_mma<<<dim3(SK_ / 128, SQ / 128, B_ * H_), blk>>>(qh, ql, kh, kl, attn);
    softmax_kernel<<<B_ * H_ * SQ, 256>>>(attn);
    pv_mma<<<dim3(SQ / 128, B_ * H_), blk>>>(attn, vh, vl, ctx);

    linear_mma<<<gl, blk>>>(ctx, Wo, bo, oproj, nullptr, nullptr, DD, DD);
    ln_kernel<<<NTOK, 128>>>(ln_g, ln_b, out);
}